// round 10
// baseline (speedup 1.0000x reference)
#include <cuda_runtime.h>

#define T_LEN 200
#define B_SZ  1024
#define D_SZ  128
#define G3    384
#define RB    8
#define WSTR  132   // weight row stride (floats) -> conflict-free LDS.128

// Precomputed x-side: [T*B][384] = (xWau+bau | xWar+bar | xWac+bac)
__device__ float g_X[(size_t)T_LEN * B_SZ * G3];

// ---------- packed fp32 helpers (Blackwell f32x2) ----------
__device__ __forceinline__ void fma2(unsigned long long &d,
                                     unsigned long long a,
                                     unsigned long long b) {
    asm("fma.rn.f32x2 %0, %1, %2, %0;" : "+l"(d) : "l"(a), "l"(b));
}
__device__ __forceinline__ unsigned long long pack2(float x, float y) {
    unsigned long long r;
    asm("mov.b64 %0, {%1, %2};" : "=l"(r) : "f"(x), "f"(y));
    return r;
}
__device__ __forceinline__ void unpack2(unsigned long long v, float &lo, float &hi) {
    asm("mov.b64 {%0, %1}, %2;" : "=f"(lo), "=f"(hi) : "l"(v));
}
__device__ __forceinline__ float sum2(unsigned long long v) {
    float lo, hi; unpack2(v, lo, hi); return lo + hi;
}

// =====================================================================
// Kernel 1: X-side GEMM (UNCHANGED from the passing R4/R6 kernel).
// =====================================================================
#define TM 64
#define TN 64
#define TK 64
#define ASTR 68
#define BSTR 68

__global__ __launch_bounds__(256) void gemm_x(
    const float* __restrict__ Xin,
    const float* __restrict__ Wau, const float* __restrict__ bau,
    const float* __restrict__ War, const float* __restrict__ bar,
    const float* __restrict__ Wac, const float* __restrict__ bac)
{
    __shared__ float As[TM * ASTR];
    __shared__ float Bs[TK * BSTR];

    const int tid = threadIdx.x;
    const int tx = tid & 15;
    const int ty = tid >> 4;
    const int m0 = blockIdx.x * TM;
    const int n0 = blockIdx.y * TN;
    const int gate = n0 >> 7;
    const int cg = n0 & 127;

    const float* W    = (gate == 0) ? Wau : ((gate == 1) ? War : Wac);
    const float* bias = (gate == 0) ? bau : ((gate == 1) ? bar : bac);

    unsigned long long acc[4][2];
    #pragma unroll
    for (int i = 0; i < 4; i++) { acc[i][0] = 0ULL; acc[i][1] = 0ULL; }

    for (int k0 = 0; k0 < D_SZ; k0 += TK) {
        #pragma unroll
        for (int l = 0; l < 4; l++) {
            int idx = tid + l * 256;
            int row = idx >> 4;
            int c4  = idx & 15;
            float4 av = *(const float4*)(Xin + (size_t)(m0 + row) * D_SZ + k0 + c4 * 4);
            *(float4*)(As + row * ASTR + c4 * 4) = av;
            float4 bv = *(const float4*)(W + (size_t)(k0 + row) * D_SZ + cg + c4 * 4);
            *(float4*)(Bs + row * BSTR + c4 * 4) = bv;
        }
        __syncthreads();

        #pragma unroll 16
        for (int kk = 0; kk < TK; kk++) {
            unsigned long long b0 = *(const unsigned long long*)(Bs + kk * BSTR + tx * 4);
            unsigned long long b1 = *(const unsigned long long*)(Bs + kk * BSTR + tx * 4 + 2);
            #pragma unroll
            for (int i = 0; i < 4; i++) {
                float a = As[(ty * 4 + i) * ASTR + kk];
                unsigned long long a2 = pack2(a, a);
                fma2(acc[i][0], a2, b0);
                fma2(acc[i][1], a2, b1);
            }
        }
        __syncthreads();
    }

    float b0f = bias[cg + tx * 4 + 0];
    float b1f = bias[cg + tx * 4 + 1];
    float b2f = bias[cg + tx * 4 + 2];
    float b3f = bias[cg + tx * 4 + 3];
    #pragma unroll
    for (int i = 0; i < 4; i++) {
        int m = m0 + ty * 4 + i;
        float v0, v1, v2, v3;
        unpack2(acc[i][0], v0, v1);
        unpack2(acc[i][1], v2, v3);
        float4 o = make_float4(v0 + b0f, v1 + b1f, v2 + b2f, v3 + b3f);
        *(float4*)(g_X + (size_t)m * G3 + n0 + tx * 4) = o;
    }
}

// =====================================================================
// Kernel 2: recurrence, GATE-SPLIT. 128 blocks x 8 rows, 384 threads.
//   group g = tid/128 (gate u / r / c), d = tid%128.
// Each weight value is read ONCE per CTA per step (196KB -> 1536 crossbar
// cyc), below the 3072-cyc FMA2 floor. 3 warps/SMSP hide LDS latency.
// Group 0: u_ = att*sigmoid(hu) -> smem gu.
// Group 1: r  = sigmoid(hr)     -> smem gr.
// Group 2: dc = s@Wbc (regs), owns state registers, does the final update.
// Single state buffer: barrier1 ends all reads, group2 writes in place,
// barrier2 publishes.
// =====================================================================
extern __shared__ float smem_rec[];

__global__ __launch_bounds__(384, 1) void augru_rec(
    const float* __restrict__ state, const float* __restrict__ att,
    const float* __restrict__ mask,
    const float* __restrict__ Wbu, const float* __restrict__ Wbr,
    const float* __restrict__ Wbc,
    float* __restrict__ out)
{
    float* WsT = smem_rec;                       // [384][132]
    float* sb  = smem_rec + G3 * WSTR;           // [8][128] state (single buffer)
    float* gu  = sb + RB * 128;                  // [8][128] a*sigmoid(hu)
    float* gr  = gu + RB * 128;                  // [8][128] sigmoid(hr)
    const int tid = threadIdx.x;
    const int grp = tid >> 7;                    // 0=u, 1=r, 2=c
    const int d   = tid & 127;
    const int b0  = blockIdx.x * RB;

    // Transposed weight load: coalesced gmem reads.
    #pragma unroll
    for (int g = 0; g < 3; g++) {
        const float* W = (g == 0) ? Wbu : ((g == 1) ? Wbr : Wbc);
        for (int i = tid; i < D_SZ * D_SZ; i += 384) {
            int k = i >> 7;
            int n = i & 127;
            WsT[(g * 128 + n) * WSTR + k] = W[i];
        }
    }

    // Initial state into smem; group 2 also keeps it in registers.
    float s_reg[RB];
    if (grp == 2) {
        #pragma unroll
        for (int r = 0; r < RB; r++) {
            s_reg[r] = state[(size_t)(b0 + r) * D_SZ + d];
            sb[r * 128 + d] = s_reg[r];
        }
    }
    __syncthreads();

    // This group's transposed weight row (its gate, its output column d).
    const float* wp = WsT + (size_t)(grp * 128 + d) * WSTR;

    for (int t = 0; t < T_LEN; t++) {
        // Prefetch this group's x-side values (+ att for grp0, mask for grp2);
        // consumed after the ~3k-cycle dot loop -> DRAM latency hidden.
        const float* Xt = g_X + ((size_t)t * B_SZ + b0) * G3 + grp * 128 + d;
        float xg[RB], aux[RB];
        #pragma unroll
        for (int r = 0; r < RB; r++) {
            xg[r] = Xt[r * G3];
            if (grp == 0)      aux[r] = __ldg(att + (size_t)t * B_SZ + b0 + r);
            else if (grp == 2) aux[r] = __ldg(mask + (size_t)(b0 + r) * T_LEN + t);
        }

        unsigned long long acc[RB];
        #pragma unroll
        for (int r = 0; r < RB; r++) acc[r] = 0ULL;

        #pragma unroll 8
        for (int k4 = 0; k4 < 32; k4++) {
            ulonglong2 w = *(const ulonglong2*)(wp + 4 * k4);
            #pragma unroll
            for (int r = 0; r < RB; r++) {
                ulonglong2 s2 = *(const ulonglong2*)(sb + r * 128 + 4 * k4);
                fma2(acc[r], w.x, s2.x);
                fma2(acc[r], w.y, s2.y);
            }
        }

        if (grp == 0) {
            #pragma unroll
            for (int r = 0; r < RB; r++) {
                float hu = xg[r] + sum2(acc[r]);
                float ug = __fdividef(1.0f, 1.0f + __expf(-hu));
                gu[r * 128 + d] = aux[r] * ug;       // a * u
            }
        } else if (grp == 1) {
            #pragma unroll
            for (int r = 0; r < RB; r++) {
                float hr = xg[r] + sum2(acc[r]);
                gr[r * 128 + d] = __fdividef(1.0f, 1.0f + __expf(-hr));
            }
        }
        __syncthreads();   // dots done; gu/gr published; all state reads done.

        if (grp == 2) {
            #pragma unroll
            for (int r = 0; r < RB; r++) {
                float dc = sum2(acc[r]);             // s @ Wbc
                float hc = xg[r] + gr[r * 128 + d] * dc;
                float e2 = __expf(2.0f * hc);
                float cd = 1.0f - __fdividef(2.0f, e2 + 1.0f);   // tanh(hc)
                float sn = s_reg[r] + aux[r] * gu[r * 128 + d] * (cd - s_reg[r]);
                s_reg[r] = sn;
                sb[r * 128 + d] = sn;                // in-place update (safe)
            }
        }
        __syncthreads();   // new state visible to everyone.
    }

    if (grp == 2) {
        #pragma unroll
        for (int r = 0; r < RB; r++)
            out[(size_t)(b0 + r) * D_SZ + d] = s_reg[r];
    }
}

// =====================================================================
extern "C" void kernel_launch(void* const* d_in, const int* in_sizes, int n_in,
                              void* d_out, int out_size)
{
    const float* inputs = (const float*)d_in[0];
    const float* state  = (const float*)d_in[1];
    const float* att    = (const float*)d_in[2];
    const float* mask   = (const float*)d_in[3];
    int w = (n_in >= 14) ? 5 : 4;
    const float* Wau = (const float*)d_in[w + 0];
    const float* bau = (const float*)d_in[w + 1];
    const float* Wbu = (const float*)d_in[w + 2];
    const float* War = (const float*)d_in[w + 3];
    const float* bar = (const float*)d_in[w + 4];
    const float* Wbr = (const float*)d_in[w + 5];
    const float* Wac = (const float*)d_in[w + 6];
    const float* bac = (const float*)d_in[w + 7];
    const float* Wbc = (const float*)d_in[w + 8];
    float* out = (float*)d_out;
    (void)in_sizes; (void)out_size;

    dim3 g1(T_LEN * B_SZ / TM, G3 / TN);   // (3200, 6)
    gemm_x<<<g1, 256>>>(inputs, Wau, bau, War, bar, Wac, bac);

    // smem: weights 384*132 + state 8*128 + gu 8*128 + gr 8*128 floats
    size_t smem = (size_t)(G3 * WSTR + 3 * RB * 128) * sizeof(float); // 215,040 B
    cudaFuncSetAttribute(augru_rec, cudaFuncAttributeMaxDynamicSharedMemorySize,
                         (int)smem);
    augru_rec<<<B_SZ / RB, 384, smem>>>(state, att, mask, Wbu, Wbr, Wbc, out);
}

// round 12
// speedup vs baseline: 1.5709x; 1.5709x over previous
#include <cuda_runtime.h>
#include <cuda_bf16.h>
#include <cstdint>

#define T_LEN 200
#define B_SZ  1024
#define D_SZ  128
#define G3    384
#define RB    8
#define WSTR  132   // recurrence weight row stride (floats) -> conflict-free LDS.128

// Precomputed x-side: [T*B][384] = (xWau+bau | xWar+bar | xWac+bac)
__device__ float g_X[(size_t)T_LEN * B_SZ * G3];

// ---------- packed fp32 helpers (Blackwell f32x2) ----------
__device__ __forceinline__ void fma2(unsigned long long &d,
                                     unsigned long long a,
                                     unsigned long long b) {
    asm("fma.rn.f32x2 %0, %1, %2, %0;" : "+l"(d) : "l"(a), "l"(b));
}
__device__ __forceinline__ void unpack2(unsigned long long v, float &lo, float &hi) {
    asm("mov.b64 {%0, %1}, %2;" : "=f"(lo), "=f"(hi) : "l"(v));
}
__device__ __forceinline__ float sum2(unsigned long long v) {
    float lo, hi; unpack2(v, lo, hi); return lo + hi;
}

// ---------- tensor-core helpers ----------
__device__ __forceinline__ void ldsm4(uint32_t* r, const void* p) {
    uint32_t a = (uint32_t)__cvta_generic_to_shared(p);
    asm volatile("ldmatrix.sync.aligned.m8n8.x4.shared.b16 {%0,%1,%2,%3}, [%4];"
                 : "=r"(r[0]), "=r"(r[1]), "=r"(r[2]), "=r"(r[3]) : "r"(a));
}
__device__ __forceinline__ void ldsm4t(uint32_t* r, const void* p) {
    uint32_t a = (uint32_t)__cvta_generic_to_shared(p);
    asm volatile("ldmatrix.sync.aligned.m8n8.x4.trans.shared.b16 {%0,%1,%2,%3}, [%4];"
                 : "=r"(r[0]), "=r"(r[1]), "=r"(r[2]), "=r"(r[3]) : "r"(a));
}
__device__ __forceinline__ void mma_bf16(float* c, const uint32_t* a,
                                         uint32_t b0, uint32_t b1) {
    asm volatile(
        "mma.sync.aligned.m16n8k16.row.col.f32.bf16.bf16.f32 "
        "{%0,%1,%2,%3}, {%4,%5,%6,%7}, {%8,%9}, {%0,%1,%2,%3};"
        : "+f"(c[0]), "+f"(c[1]), "+f"(c[2]), "+f"(c[3])
        : "r"(a[0]), "r"(a[1]), "r"(a[2]), "r"(a[3]), "r"(b0), "r"(b1));
}

// =====================================================================
// Kernel 1: X-side GEMM on tensor cores, bf16-split (hi/lo, 3 products).
// Per block: M=64 rows of X, N=128 (one gate), K=128 (whole reduction).
// 256 threads = 8 warps, warp grid 2(m) x 4(n), warp tile 32x32.
// smem: A hi/lo [64][136] + B hi/lo [128][136] halfs = 104,448 B -> 2 CTA/SM.
// C = Ah*Bh + Ah*Bl + Al*Bh  (fp32 accum)  => ~2^-16 relative error.
// =====================================================================
#define GBM  64
#define GSTR 136   // half stride: 272B rows -> conflict-free ldmatrix

__global__ __launch_bounds__(256) void gemm_x_mma(
    const float* __restrict__ Xin,
    const float* __restrict__ Wau, const float* __restrict__ bau,
    const float* __restrict__ War, const float* __restrict__ bar,
    const float* __restrict__ Wac, const float* __restrict__ bac)
{
    extern __shared__ __nv_bfloat16 smg[];
    __nv_bfloat16* Ah = smg;                    // [GBM][GSTR]
    __nv_bfloat16* Al = Ah + GBM * GSTR;
    __nv_bfloat16* Bh = Al + GBM * GSTR;        // [128][GSTR]
    __nv_bfloat16* Bl = Bh + 128 * GSTR;

    const int tid  = threadIdx.x;
    const int m0   = blockIdx.x * GBM;
    const int gate = blockIdx.y;
    const float* W    = (gate == 0) ? Wau : ((gate == 1) ? War : Wac);
    const float* bias = (gate == 0) ? bau : ((gate == 1) ? bar : bac);

    // ---- load + convert A (64x128 fp32 -> bf16 hi/lo) ----
    #pragma unroll
    for (int l = 0; l < 8; l++) {
        int idx = tid + l * 256;            // 2048 float4 slots
        int row = idx >> 5;
        int c4  = idx & 31;
        float4 v = *(const float4*)(Xin + (size_t)(m0 + row) * D_SZ + c4 * 4);
        float vv[4] = {v.x, v.y, v.z, v.w};
        #pragma unroll
        for (int j = 0; j < 4; j++) {
            __nv_bfloat16 h = __float2bfloat16(vv[j]);
            Ah[row * GSTR + c4 * 4 + j] = h;
            Al[row * GSTR + c4 * 4 + j] =
                __float2bfloat16(vv[j] - __bfloat162float(h));
        }
    }
    // ---- load + convert B = W gate (128x128) ----
    #pragma unroll
    for (int l = 0; l < 16; l++) {
        int idx = tid + l * 256;            // 4096 float4 slots
        int row = idx >> 5;
        int c4  = idx & 31;
        float4 v = *(const float4*)(W + (size_t)row * D_SZ + c4 * 4);
        float vv[4] = {v.x, v.y, v.z, v.w};
        #pragma unroll
        for (int j = 0; j < 4; j++) {
            __nv_bfloat16 h = __float2bfloat16(vv[j]);
            Bh[row * GSTR + c4 * 4 + j] = h;
            Bl[row * GSTR + c4 * 4 + j] =
                __float2bfloat16(vv[j] - __bfloat162float(h));
        }
    }
    __syncthreads();

    const int lane = tid & 31;
    const int wid  = tid >> 5;
    const int wm   = wid & 1;     // m offset 32*wm
    const int wn   = wid >> 1;    // n offset 32*wn

    float c[2][4][4];
    #pragma unroll
    for (int mt = 0; mt < 2; mt++)
        #pragma unroll
        for (int nt = 0; nt < 4; nt++)
            #pragma unroll
            for (int j = 0; j < 4; j++) c[mt][nt][j] = 0.0f;

    const int lr = lane & 15;
    const int lc = (lane >> 4) * 8;

    #pragma unroll
    for (int kc = 0; kc < 8; kc++) {
        uint32_t ah[2][4], al[2][4], bh[2][4], bl[2][4];
        #pragma unroll
        for (int mt = 0; mt < 2; mt++) {
            const __nv_bfloat16* pa =
                Ah + (wm * 32 + mt * 16 + lr) * GSTR + kc * 16 + lc;
            ldsm4(ah[mt], pa);
            ldsm4(al[mt], pa + (Al - Ah));
        }
        #pragma unroll
        for (int bt = 0; bt < 2; bt++) {
            const __nv_bfloat16* pb =
                Bh + (kc * 16 + lr) * GSTR + wn * 32 + bt * 16 + lc;
            ldsm4t(bh[bt], pb);
            ldsm4t(bl[bt], pb + (Bl - Bh));
        }
        #pragma unroll
        for (int mt = 0; mt < 2; mt++)
            #pragma unroll
            for (int bt = 0; bt < 2; bt++)
                #pragma unroll
                for (int h = 0; h < 2; h++) {
                    float* cc = c[mt][bt * 2 + h];
                    mma_bf16(cc, ah[mt], bh[bt][2 * h], bh[bt][2 * h + 1]);
                    mma_bf16(cc, ah[mt], bl[bt][2 * h], bl[bt][2 * h + 1]);
                    mma_bf16(cc, al[mt], bh[bt][2 * h], bh[bt][2 * h + 1]);
                }
    }

    // ---- epilogue: add bias, store to g_X ----
    const int mrow = lane >> 2;
    const int ncol = (lane & 3) * 2;
    #pragma unroll
    for (int mt = 0; mt < 2; mt++) {
        #pragma unroll
        for (int nt = 0; nt < 4; nt++) {
            int n = wn * 32 + nt * 8 + ncol;
            float b0 = __ldg(bias + n);
            float b1 = __ldg(bias + n + 1);
            int m = m0 + wm * 32 + mt * 16 + mrow;
            float* o0 = g_X + (size_t)m * G3 + gate * 128 + n;
            *(float2*)o0 = make_float2(c[mt][nt][0] + b0, c[mt][nt][1] + b1);
            float* o1 = g_X + (size_t)(m + 8) * G3 + gate * 128 + n;
            *(float2*)o1 = make_float2(c[mt][nt][2] + b0, c[mt][nt][3] + b1);
        }
    }
}

// =====================================================================
// Kernel 2: recurrence — EXACT best-known (R6, 642us) version.
// 128 blocks x 8 rows, 256 threads; rg=tid>>7 owns 4 rows, full K.
// =====================================================================
extern __shared__ float smem_rec[];

__global__ __launch_bounds__(256, 1) void augru_rec(
    const float* __restrict__ state, const float* __restrict__ att,
    const float* __restrict__ mask,
    const float* __restrict__ Wbu, const float* __restrict__ Wbr,
    const float* __restrict__ Wbc,
    float* __restrict__ out)
{
    float* WsT = smem_rec;                       // [384][132]
    float* sb  = smem_rec + G3 * WSTR;           // [2][8][128]
    const int tid = threadIdx.x;
    const int rg  = tid >> 7;
    const int d   = tid & 127;
    const int b0  = blockIdx.x * RB;

    #pragma unroll
    for (int g = 0; g < 3; g++) {
        const float* W = (g == 0) ? Wbu : ((g == 1) ? Wbr : Wbc);
        for (int i = tid; i < D_SZ * D_SZ; i += 256) {
            int k = i >> 7;
            int n = i & 127;
            WsT[(g * 128 + n) * WSTR + k] = W[i];
        }
    }

    float s_reg[4];
    #pragma unroll
    for (int rr = 0; rr < 4; rr++) {
        int ro = rg * 4 + rr;
        s_reg[rr] = state[(size_t)(b0 + ro) * D_SZ + d];
        sb[ro * 128 + d] = s_reg[rr];
    }
    __syncthreads();

    const float* wu = WsT + (size_t)d * WSTR;
    const float* wr = WsT + (size_t)(128 + d) * WSTR;
    const float* wc = WsT + (size_t)(256 + d) * WSTR;

    int cur = 0;
    for (int t = 0; t < T_LEN; t++) {
        const float* Xt = g_X + ((size_t)t * B_SZ + b0) * G3;
        float xu[4], xr[4], xc[4], am[4], mm[4];
        #pragma unroll
        for (int rr = 0; rr < 4; rr++) {
            int ro = rg * 4 + rr;
            xu[rr] = Xt[ro * G3 + d];
            xr[rr] = Xt[ro * G3 + 128 + d];
            xc[rr] = Xt[ro * G3 + 256 + d];
            am[rr] = __ldg(att + (size_t)t * B_SZ + b0 + ro);
            mm[rr] = __ldg(mask + (size_t)(b0 + ro) * T_LEN + t);
        }

        unsigned long long au[4], ar[4], ac[4];
        #pragma unroll
        for (int rr = 0; rr < 4; rr++) { au[rr] = 0ULL; ar[rr] = 0ULL; ac[rr] = 0ULL; }

        const float* srow = sb + cur * (RB * 128) + rg * 4 * 128;
        #pragma unroll 8
        for (int k4 = 0; k4 < 32; k4++) {
            ulonglong2 w_u = *(const ulonglong2*)(wu + 4 * k4);
            ulonglong2 w_r = *(const ulonglong2*)(wr + 4 * k4);
            ulonglong2 w_c = *(const ulonglong2*)(wc + 4 * k4);
            #pragma unroll
            for (int rr = 0; rr < 4; rr++) {
                ulonglong2 s2 = *(const ulonglong2*)(srow + rr * 128 + 4 * k4);
                fma2(au[rr], w_u.x, s2.x);
                fma2(au[rr], w_u.y, s2.y);
                fma2(ar[rr], w_r.x, s2.x);
                fma2(ar[rr], w_r.y, s2.y);
                fma2(ac[rr], w_c.x, s2.x);
                fma2(ac[rr], w_c.y, s2.y);
            }
        }

        const int nxt = cur ^ 1;
        float* dst = sb + nxt * (RB * 128);
        #pragma unroll
        for (int rr = 0; rr < 4; rr++) {
            int ro = rg * 4 + rr;
            float hu = xu[rr] + sum2(au[rr]);
            float hr = xr[rr] + sum2(ar[rr]);
            float dc = sum2(ac[rr]);
            float ug  = __fdividef(1.0f, 1.0f + __expf(-hu));
            float rg_ = __fdividef(1.0f, 1.0f + __expf(-hr));
            float hc = xc[rr] + rg_ * dc;
            float e2 = __expf(2.0f * hc);
            float cd = 1.0f - __fdividef(2.0f, e2 + 1.0f);   // tanh(hc)
            float ua = am[rr] * ug;
            float sn = s_reg[rr] + mm[rr] * ua * (cd - s_reg[rr]);
            s_reg[rr] = sn;
            dst[ro * 128 + d] = sn;
        }
        cur = nxt;
        __syncthreads();
    }

    #pragma unroll
    for (int rr = 0; rr < 4; rr++) {
        int ro = rg * 4 + rr;
        out[(size_t)(b0 + ro) * D_SZ + d] = s_reg[rr];
    }
}

// =====================================================================
extern "C" void kernel_launch(void* const* d_in, const int* in_sizes, int n_in,
                              void* d_out, int out_size)
{
    const float* inputs = (const float*)d_in[0];
    const float* state  = (const float*)d_in[1];
    const float* att    = (const float*)d_in[2];
    const float* mask   = (const float*)d_in[3];
    int w = (n_in >= 14) ? 5 : 4;
    const float* Wau = (const float*)d_in[w + 0];
    const float* bau = (const float*)d_in[w + 1];
    const float* Wbu = (const float*)d_in[w + 2];
    const float* War = (const float*)d_in[w + 3];
    const float* bar = (const float*)d_in[w + 4];
    const float* Wbr = (const float*)d_in[w + 5];
    const float* Wac = (const float*)d_in[w + 6];
    const float* bac = (const float*)d_in[w + 7];
    const float* Wbc = (const float*)d_in[w + 8];
    float* out = (float*)d_out;
    (void)in_sizes; (void)out_size;

    // Tensor-core x-side GEMM: grid (3200, 3)
    size_t gsm = (size_t)(2 * GBM * GSTR + 2 * 128 * GSTR) * sizeof(__nv_bfloat16);
    cudaFuncSetAttribute(gemm_x_mma, cudaFuncAttributeMaxDynamicSharedMemorySize,
                         (int)gsm);
    dim3 g1(T_LEN * B_SZ / GBM, 3);
    gemm_x_mma<<<g1, 256, gsm>>>(inputs, Wau, bau, War, bar, Wac, bac);

    // Recurrence (R6 best-known)
    size_t smem = (size_t)(G3 * WSTR + 2 * RB * 128) * sizeof(float);
    cudaFuncSetAttribute(augru_rec, cudaFuncAttributeMaxDynamicSharedMemorySize,
                         (int)smem);
    augru_rec<<<B_SZ / RB, 256, smem>>>(state, att, mask, Wbu, Wbr, Wbc, out);
}

// round 13
// speedup vs baseline: 2.4437x; 1.5556x over previous
#include <cuda_runtime.h>
#include <cuda_bf16.h>
#include <cstdint>

#define T_LEN 200
#define B_SZ  1024
#define D_SZ  128
#define G3    384
#define RB    8
#define SSTR  24    // state row stride (halfs): 48B, 16B-aligned, conflict-free

// Precomputed x-side: [T*B][384] = (xWau+bau | xWar+bar | xWac+bac)
__device__ float g_X[(size_t)T_LEN * B_SZ * G3];

// ---------- tensor-core helpers ----------
__device__ __forceinline__ void ldsm4(uint32_t* r, const void* p) {
    uint32_t a = (uint32_t)__cvta_generic_to_shared(p);
    asm volatile("ldmatrix.sync.aligned.m8n8.x4.shared.b16 {%0,%1,%2,%3}, [%4];"
                 : "=r"(r[0]), "=r"(r[1]), "=r"(r[2]), "=r"(r[3]) : "r"(a));
}
__device__ __forceinline__ void ldsm4t(uint32_t* r, const void* p) {
    uint32_t a = (uint32_t)__cvta_generic_to_shared(p);
    asm volatile("ldmatrix.sync.aligned.m8n8.x4.trans.shared.b16 {%0,%1,%2,%3}, [%4];"
                 : "=r"(r[0]), "=r"(r[1]), "=r"(r[2]), "=r"(r[3]) : "r"(a));
}
__device__ __forceinline__ void ldsm2t(uint32_t* r, const void* p) {
    uint32_t a = (uint32_t)__cvta_generic_to_shared(p);
    asm volatile("ldmatrix.sync.aligned.m8n8.x2.trans.shared.b16 {%0,%1}, [%2];"
                 : "=r"(r[0]), "=r"(r[1]) : "r"(a));
}
__device__ __forceinline__ void mma_bf16(float* c, const uint32_t* a,
                                         uint32_t b0, uint32_t b1) {
    asm volatile(
        "mma.sync.aligned.m16n8k16.row.col.f32.bf16.bf16.f32 "
        "{%0,%1,%2,%3}, {%4,%5,%6,%7}, {%8,%9}, {%0,%1,%2,%3};"
        : "+f"(c[0]), "+f"(c[1]), "+f"(c[2]), "+f"(c[3])
        : "r"(a[0]), "r"(a[1]), "r"(a[2]), "r"(a[3]), "r"(b0), "r"(b1));
}
__device__ __forceinline__ void bf16split(float v, __nv_bfloat16& h, __nv_bfloat16& l) {
    h = __float2bfloat16(v);
    l = __float2bfloat16(v - __bfloat162float(h));
}

// =====================================================================
// Kernel 1: X-side GEMM on tensor cores, bf16-split (UNCHANGED, validated).
// =====================================================================
#define GBM  64
#define GSTR 136

__global__ __launch_bounds__(256) void gemm_x_mma(
    const float* __restrict__ Xin,
    const float* __restrict__ Wau, const float* __restrict__ bau,
    const float* __restrict__ War, const float* __restrict__ bar,
    const float* __restrict__ Wac, const float* __restrict__ bac)
{
    extern __shared__ __nv_bfloat16 smg[];
    __nv_bfloat16* Ah = smg;
    __nv_bfloat16* Al = Ah + GBM * GSTR;
    __nv_bfloat16* Bh = Al + GBM * GSTR;
    __nv_bfloat16* Bl = Bh + 128 * GSTR;

    const int tid  = threadIdx.x;
    const int m0   = blockIdx.x * GBM;
    const int gate = blockIdx.y;
    const float* W    = (gate == 0) ? Wau : ((gate == 1) ? War : Wac);
    const float* bias = (gate == 0) ? bau : ((gate == 1) ? bar : bac);

    #pragma unroll
    for (int l = 0; l < 8; l++) {
        int idx = tid + l * 256;
        int row = idx >> 5;
        int c4  = idx & 31;
        float4 v = *(const float4*)(Xin + (size_t)(m0 + row) * D_SZ + c4 * 4);
        float vv[4] = {v.x, v.y, v.z, v.w};
        #pragma unroll
        for (int j = 0; j < 4; j++) {
            __nv_bfloat16 h, lo; bf16split(vv[j], h, lo);
            Ah[row * GSTR + c4 * 4 + j] = h;
            Al[row * GSTR + c4 * 4 + j] = lo;
        }
    }
    #pragma unroll
    for (int l = 0; l < 16; l++) {
        int idx = tid + l * 256;
        int row = idx >> 5;
        int c4  = idx & 31;
        float4 v = *(const float4*)(W + (size_t)row * D_SZ + c4 * 4);
        float vv[4] = {v.x, v.y, v.z, v.w};
        #pragma unroll
        for (int j = 0; j < 4; j++) {
            __nv_bfloat16 h, lo; bf16split(vv[j], h, lo);
            Bh[row * GSTR + c4 * 4 + j] = h;
            Bl[row * GSTR + c4 * 4 + j] = lo;
        }
    }
    __syncthreads();

    const int lane = tid & 31;
    const int wid  = tid >> 5;
    const int wm   = wid & 1;
    const int wn   = wid >> 1;

    float c[2][4][4];
    #pragma unroll
    for (int mt = 0; mt < 2; mt++)
        #pragma unroll
        for (int nt = 0; nt < 4; nt++)
            #pragma unroll
            for (int j = 0; j < 4; j++) c[mt][nt][j] = 0.0f;

    const int lr = lane & 15;
    const int lc = (lane >> 4) * 8;

    #pragma unroll
    for (int kc = 0; kc < 8; kc++) {
        uint32_t ah[2][4], al[2][4], bh[2][4], bl[2][4];
        #pragma unroll
        for (int mt = 0; mt < 2; mt++) {
            const __nv_bfloat16* pa =
                Ah + (wm * 32 + mt * 16 + lr) * GSTR + kc * 16 + lc;
            ldsm4(ah[mt], pa);
            ldsm4(al[mt], pa + (Al - Ah));
        }
        #pragma unroll
        for (int bt = 0; bt < 2; bt++) {
            const __nv_bfloat16* pb =
                Bh + (kc * 16 + lr) * GSTR + wn * 32 + bt * 16 + lc;
            ldsm4t(bh[bt], pb);
            ldsm4t(bl[bt], pb + (Bl - Bh));
        }
        #pragma unroll
        for (int mt = 0; mt < 2; mt++)
            #pragma unroll
            for (int bt = 0; bt < 2; bt++)
                #pragma unroll
                for (int h = 0; h < 2; h++) {
                    float* cc = c[mt][bt * 2 + h];
                    mma_bf16(cc, ah[mt], bh[bt][2 * h], bh[bt][2 * h + 1]);
                    mma_bf16(cc, ah[mt], bl[bt][2 * h], bl[bt][2 * h + 1]);
                    mma_bf16(cc, al[mt], bh[bt][2 * h], bh[bt][2 * h + 1]);
                }
    }

    const int mrow = lane >> 2;
    const int ncol = (lane & 3) * 2;
    #pragma unroll
    for (int mt = 0; mt < 2; mt++) {
        #pragma unroll
        for (int nt = 0; nt < 4; nt++) {
            int n = wn * 32 + nt * 8 + ncol;
            float b0 = __ldg(bias + n);
            float b1 = __ldg(bias + n + 1);
            int m = m0 + wm * 32 + mt * 16 + mrow;
            float* o0 = g_X + (size_t)m * G3 + gate * 128 + n;
            *(float2*)o0 = make_float2(c[mt][nt][0] + b0, c[mt][nt][1] + b1);
            float* o1 = g_X + (size_t)(m + 8) * G3 + gate * 128 + n;
            *(float2*)o1 = make_float2(c[mt][nt][2] + b0, c[mt][nt][3] + b1);
        }
    }
}

// =====================================================================
// Kernel 2: recurrence on TENSOR CORES.
// 128 CTAs x 8 rows, 256 threads (8 warps).
// Per step: acc[3 gates][16 d] x 8 rows = W^T(384x128 mma-A) @ s(128x8 mma-B),
// bf16 hi/lo 3-product split, fp32 accum.
// Warp w owns d in [16w,16w+16) across ALL 3 gates -> gate math lane-local.
// Old state in registers (fixed (d,row)<->lane map). One barrier/step.
// smem: W hi/lo [384][128] halfs XOR-swizzled; state hi/lo [2][128][24].
// =====================================================================
extern __shared__ __nv_bfloat16 smr[];

__global__ __launch_bounds__(256, 1) void augru_rec_mma(
    const float* __restrict__ state, const float* __restrict__ att,
    const float* __restrict__ mask,
    const float* __restrict__ Wbu, const float* __restrict__ Wbr,
    const float* __restrict__ Wbc,
    float* __restrict__ out)
{
    __nv_bfloat16* Wh = smr;                    // [384][128] swizzled
    __nv_bfloat16* Wl = Wh + G3 * 128;
    __nv_bfloat16* Sh = Wl + G3 * 128;          // [2][128][SSTR]
    __nv_bfloat16* Sl = Sh + 2 * 128 * SSTR;

    const int tid  = threadIdx.x;
    const int lane = tid & 31;
    const int w    = tid >> 5;
    const int b0   = blockIdx.x * RB;

    // ---- weights: transpose + bf16-split into swizzled smem ----
    // WbT[m = gate*128 + n][k] = W[k][n];  phys: m*128 + ((k>>3)^(m&7))*8 + (k&7)
    #pragma unroll
    for (int g = 0; g < 3; g++) {
        const float* W = (g == 0) ? Wbu : ((g == 1) ? Wbr : Wbc);
        for (int i = tid; i < 128 * 64; i += 256) {
            int m  = i & 127;            // output dim (coalesced LDG over m)
            int k2 = (i >> 7) * 2;       // even k
            float v0 = W[(size_t)k2 * D_SZ + m];
            float v1 = W[(size_t)(k2 + 1) * D_SZ + m];
            __nv_bfloat16 h0, l0, h1, l1;
            bf16split(v0, h0, l0);
            bf16split(v1, h1, l1);
            int off = (g * 128 + m) * 128 + (((k2 >> 3) ^ (m & 7)) << 3) + (k2 & 7);
            __nv_bfloat162 ph; ph.x = h0; ph.y = h1;
            __nv_bfloat162 pl; pl.x = l0; pl.y = l1;
            *(__nv_bfloat162*)(Wh + off) = ph;
            *(__nv_bfloat162*)(Wl + off) = pl;
        }
    }

    // ---- lane ownership: d0/d1 x rows n0/n1 (matches mma acc layout) ----
    const int d0 = 16 * w + (lane >> 2);
    const int d1 = d0 + 8;
    const int n0 = (lane & 3) * 2;
    const int n1 = n0 + 1;

    float s_reg[4];
    s_reg[0] = state[(size_t)(b0 + n0) * D_SZ + d0];
    s_reg[1] = state[(size_t)(b0 + n1) * D_SZ + d0];
    s_reg[2] = state[(size_t)(b0 + n0) * D_SZ + d1];
    s_reg[3] = state[(size_t)(b0 + n1) * D_SZ + d1];

    // write initial state (buffer 0) as bf16 hi/lo pairs
    {
        __nv_bfloat16 h0, l0, h1, l1;
        bf16split(s_reg[0], h0, l0); bf16split(s_reg[1], h1, l1);
        __nv_bfloat162 ph; ph.x = h0; ph.y = h1;
        __nv_bfloat162 pl; pl.x = l0; pl.y = l1;
        *(__nv_bfloat162*)(Sh + d0 * SSTR + n0) = ph;
        *(__nv_bfloat162*)(Sl + d0 * SSTR + n0) = pl;
        bf16split(s_reg[2], h0, l0); bf16split(s_reg[3], h1, l1);
        ph.x = h0; ph.y = h1; pl.x = l0; pl.y = l1;
        *(__nv_bfloat162*)(Sh + d1 * SSTR + n0) = ph;
        *(__nv_bfloat162*)(Sl + d1 * SSTR + n0) = pl;
    }
    __syncthreads();

    const int lr = lane & 15;
    int cur = 0;
    for (int t = 0; t < T_LEN; t++) {
        // ---- prefetch x-side + att + mask (consumed after the mma loop) ----
        const float* Xb = g_X + ((size_t)t * B_SZ + b0) * G3;
        float xu[4], xr[4], xc[4];
        xu[0] = Xb[n0 * G3 + d0];        xu[1] = Xb[n1 * G3 + d0];
        xu[2] = Xb[n0 * G3 + d1];        xu[3] = Xb[n1 * G3 + d1];
        xr[0] = Xb[n0 * G3 + 128 + d0];  xr[1] = Xb[n1 * G3 + 128 + d0];
        xr[2] = Xb[n0 * G3 + 128 + d1];  xr[3] = Xb[n1 * G3 + 128 + d1];
        xc[0] = Xb[n0 * G3 + 256 + d0];  xc[1] = Xb[n1 * G3 + 256 + d0];
        xc[2] = Xb[n0 * G3 + 256 + d1];  xc[3] = Xb[n1 * G3 + 256 + d1];
        float a0 = __ldg(att + (size_t)t * B_SZ + b0 + n0);
        float a1 = __ldg(att + (size_t)t * B_SZ + b0 + n1);
        float k0 = __ldg(mask + (size_t)(b0 + n0) * T_LEN + t);
        float k1 = __ldg(mask + (size_t)(b0 + n1) * T_LEN + t);

        float acc[3][4];
        #pragma unroll
        for (int g = 0; g < 3; g++)
            #pragma unroll
            for (int j = 0; j < 4; j++) acc[g][j] = 0.0f;

        const __nv_bfloat16* Sbh = Sh + cur * 128 * SSTR;
        const __nv_bfloat16* Sbl = Sl + cur * 128 * SSTR;

        #pragma unroll
        for (int kc = 0; kc < 8; kc++) {
            uint32_t bh[2], bl[2];
            ldsm2t(bh, Sbh + (kc * 16 + lr) * SSTR);
            ldsm2t(bl, Sbl + (kc * 16 + lr) * SSTR);
            #pragma unroll
            for (int g = 0; g < 3; g++) {
                int mrow  = g * 128 + 16 * w + lr;
                int chunk = ((kc * 2 + (lane >> 4)) ^ (lr & 7)) << 3;
                uint32_t ah[4], al[4];
                ldsm4(ah, Wh + mrow * 128 + chunk);
                ldsm4(al, Wl + mrow * 128 + chunk);
                mma_bf16(acc[g], ah, bh[0], bh[1]);
                mma_bf16(acc[g], ah, bl[0], bl[1]);
                mma_bf16(acc[g], al, bh[0], bh[1]);
            }
        }

        // ---- gates + state update (lane-local) ----
        float sn[4];
        #pragma unroll
        for (int j = 0; j < 4; j++) {
            float hu = acc[0][j] + xu[j];
            float hr = acc[1][j] + xr[j];
            float dc = acc[2][j];
            float ug = __fdividef(1.0f, 1.0f + __expf(-hu));
            float rg = __fdividef(1.0f, 1.0f + __expf(-hr));
            float hc = xc[j] + rg * dc;
            float e2 = __expf(2.0f * hc);
            float cd = 1.0f - __fdividef(2.0f, e2 + 1.0f);   // tanh
            float av = (j & 1) ? a1 : a0;
            float mk = (j & 1) ? k1 : k0;
            sn[j] = s_reg[j] + mk * av * ug * (cd - s_reg[j]);
            s_reg[j] = sn[j];
        }

        // ---- write next state buffer (conflict-free STS.32) ----
        const int nxt = cur ^ 1;
        __nv_bfloat16* Dh = Sh + nxt * 128 * SSTR;
        __nv_bfloat16* Dl = Sl + nxt * 128 * SSTR;
        {
            __nv_bfloat16 h0, l0, h1, l1;
            bf16split(sn[0], h0, l0); bf16split(sn[1], h1, l1);
            __nv_bfloat162 ph; ph.x = h0; ph.y = h1;
            __nv_bfloat162 pl; pl.x = l0; pl.y = l1;
            *(__nv_bfloat162*)(Dh + d0 * SSTR + n0) = ph;
            *(__nv_bfloat162*)(Dl + d0 * SSTR + n0) = pl;
            bf16split(sn[2], h0, l0); bf16split(sn[3], h1, l1);
            ph.x = h0; ph.y = h1; pl.x = l0; pl.y = l1;
            *(__nv_bfloat162*)(Dh + d1 * SSTR + n0) = ph;
            *(__nv_bfloat162*)(Dl + d1 * SSTR + n0) = pl;
        }
        __syncthreads();
        cur = nxt;
    }

    out[(size_t)(b0 + n0) * D_SZ + d0] = s_reg[0];
    out[(size_t)(b0 + n1) * D_SZ + d0] = s_reg[1];
    out[(size_t)(b0 + n0) * D_SZ + d1] = s_reg[2];
    out[(size_t)(b0 + n1) * D_SZ + d1] = s_reg[3];
}

// =====================================================================
extern "C" void kernel_launch(void* const* d_in, const int* in_sizes, int n_in,
                              void* d_out, int out_size)
{
    const float* inputs = (const float*)d_in[0];
    const float* state  = (const float*)d_in[1];
    const float* att    = (const float*)d_in[2];
    const float* mask   = (const float*)d_in[3];
    int w = (n_in >= 14) ? 5 : 4;
    const float* Wau = (const float*)d_in[w + 0];
    const float* bau = (const float*)d_in[w + 1];
    const float* Wbu = (const float*)d_in[w + 2];
    const float* War = (const float*)d_in[w + 3];
    const float* bar = (const float*)d_in[w + 4];
    const float* Wbr = (const float*)d_in[w + 5];
    const float* Wac = (const float*)d_in[w + 6];
    const float* bac = (const float*)d_in[w + 7];
    const float* Wbc = (const float*)d_in[w + 8];
    float* out = (float*)d_out;
    (void)in_sizes; (void)out_size;

    // Tensor-core x-side GEMM: grid (3200, 3)
    size_t gsm = (size_t)(2 * GBM * GSTR + 2 * 128 * GSTR) * sizeof(__nv_bfloat16);
    cudaFuncSetAttribute(gemm_x_mma, cudaFuncAttributeMaxDynamicSharedMemorySize,
                         (int)gsm);
    dim3 g1(T_LEN * B_SZ / GBM, 3);
    gemm_x_mma<<<g1, 256, gsm>>>(inputs, Wau, bau, War, bar, Wac, bac);

    // Tensor-core recurrence:
    // smem = (2*384*128 + 2*2*128*24) halfs = 110,592 halfs = 221,184 B
    size_t rsm = (size_t)(2 * G3 * 128 + 4 * 128 * SSTR) * sizeof(__nv_bfloat16);
    cudaFuncSetAttribute(augru_rec_mma, cudaFuncAttributeMaxDynamicSharedMemorySize,
                         (int)rsm);
    augru_rec_mma<<<B_SZ / RB, 256, rsm>>>(state, att, mask, Wbu, Wbr, Wbc, out);
}